// round 15
// baseline (speedup 1.0000x reference)
#include <cuda_runtime.h>
#include <cuda_bf16.h>
#include <cstdint>

// Problem constants (fixed by dataset): N=50000, E=800000, IN=OUT=128, fp32.
#define MAX_N 50176
#define FT    128

__device__ float g_emb[MAX_N * FT];   // aggregated neighbor features
__device__ float g_acc[MAX_N * FT];   // partial product x @ W1

// ---------------------------------------------------------------------------
// Packed fp32x2 helpers (FFMA2 in SASS — 2x fp32 FMA throughput, bit-exact)
// ---------------------------------------------------------------------------
__device__ __forceinline__ unsigned long long fma2(unsigned long long a,
                                                   unsigned long long b,
                                                   unsigned long long c) {
    unsigned long long d;
    asm("fma.rn.f32x2 %0, %1, %2, %3;" : "=l"(d) : "l"(a), "l"(b), "l"(c));
    return d;
}
__device__ __forceinline__ unsigned long long pack2(float lo, float hi) {
    unsigned long long d;
    asm("mov.b64 %0, {%1, %2};" : "=l"(d) : "f"(lo), "f"(hi));
    return d;
}
__device__ __forceinline__ void unpack2(unsigned long long v, float& lo, float& hi) {
    asm("mov.b64 {%0, %1}, %2;" : "=f"(lo), "=f"(hi) : "l"(v));
}

// ---------------------------------------------------------------------------
// Kernel A: weighted neighbor aggregation — ONE WARP PER NODE, fused CSR
// range discovery (lanes 0/1 binary-search sorted edge_dst, shfl broadcast).
// 8-way edge unroll => 8 independent 512B x-row gathers in flight per warp.
// Runs CONCURRENTLY with gemmX on another stream: this kernel saturates the
// L2/LSU path while gemmX saturates the FMA pipe.
// ---------------------------------------------------------------------------
__global__ __launch_bounds__(256)
void agg_kernel(const float* __restrict__ x,
                const int* __restrict__ src,
                const int* __restrict__ dst,
                const float* __restrict__ wgt,
                float* __restrict__ emb, int Nn, int E) {
    int gw  = (blockIdx.x * blockDim.x + threadIdx.x) >> 5;   // warp = node
    if (gw >= Nn) return;
    int lid = threadIdx.x & 31;

    int lo = 0;
    if (lid < 2) {
        int target = gw + lid;
        int hi = E;
        while (lo < hi) {
            int mid = (lo + hi) >> 1;
            if (__ldg(&dst[mid]) < target) lo = mid + 1; else hi = mid;
        }
    }
    int start = __shfl_sync(0xffffffffu, lo, 0);
    int end   = __shfl_sync(0xffffffffu, lo, 1);

    float4 a0 = make_float4(0.f, 0.f, 0.f, 0.f);
    float4 a1 = a0, a2 = a0, a3 = a0;
    const float* xl = x + lid * 4;

    int e = start;
    int e8 = start + ((end - start) & ~7);
    for (; e < e8; e += 8) {
        int   s0 = __ldg(&src[e + 0]), s1 = __ldg(&src[e + 1]);
        int   s2 = __ldg(&src[e + 2]), s3 = __ldg(&src[e + 3]);
        int   s4 = __ldg(&src[e + 4]), s5 = __ldg(&src[e + 5]);
        int   s6 = __ldg(&src[e + 6]), s7 = __ldg(&src[e + 7]);
        float w0 = __ldg(&wgt[e + 0]), w1 = __ldg(&wgt[e + 1]);
        float w2 = __ldg(&wgt[e + 2]), w3 = __ldg(&wgt[e + 3]);
        float w4 = __ldg(&wgt[e + 4]), w5 = __ldg(&wgt[e + 5]);
        float w6 = __ldg(&wgt[e + 6]), w7 = __ldg(&wgt[e + 7]);
        float4 v0 = *reinterpret_cast<const float4*>(&xl[(size_t)s0 * FT]);
        float4 v1 = *reinterpret_cast<const float4*>(&xl[(size_t)s1 * FT]);
        float4 v2 = *reinterpret_cast<const float4*>(&xl[(size_t)s2 * FT]);
        float4 v3 = *reinterpret_cast<const float4*>(&xl[(size_t)s3 * FT]);
        float4 v4 = *reinterpret_cast<const float4*>(&xl[(size_t)s4 * FT]);
        float4 v5 = *reinterpret_cast<const float4*>(&xl[(size_t)s5 * FT]);
        float4 v6 = *reinterpret_cast<const float4*>(&xl[(size_t)s6 * FT]);
        float4 v7 = *reinterpret_cast<const float4*>(&xl[(size_t)s7 * FT]);
        a0.x = fmaf(w0, v0.x, a0.x); a0.y = fmaf(w0, v0.y, a0.y);
        a0.z = fmaf(w0, v0.z, a0.z); a0.w = fmaf(w0, v0.w, a0.w);
        a1.x = fmaf(w1, v1.x, a1.x); a1.y = fmaf(w1, v1.y, a1.y);
        a1.z = fmaf(w1, v1.z, a1.z); a1.w = fmaf(w1, v1.w, a1.w);
        a2.x = fmaf(w2, v2.x, a2.x); a2.y = fmaf(w2, v2.y, a2.y);
        a2.z = fmaf(w2, v2.z, a2.z); a2.w = fmaf(w2, v2.w, a2.w);
        a3.x = fmaf(w3, v3.x, a3.x); a3.y = fmaf(w3, v3.y, a3.y);
        a3.z = fmaf(w3, v3.z, a3.z); a3.w = fmaf(w3, v3.w, a3.w);
        a0.x = fmaf(w4, v4.x, a0.x); a0.y = fmaf(w4, v4.y, a0.y);
        a0.z = fmaf(w4, v4.z, a0.z); a0.w = fmaf(w4, v4.w, a0.w);
        a1.x = fmaf(w5, v5.x, a1.x); a1.y = fmaf(w5, v5.y, a1.y);
        a1.z = fmaf(w5, v5.z, a1.z); a1.w = fmaf(w5, v5.w, a1.w);
        a2.x = fmaf(w6, v6.x, a2.x); a2.y = fmaf(w6, v6.y, a2.y);
        a2.z = fmaf(w6, v6.z, a2.z); a2.w = fmaf(w6, v6.w, a2.w);
        a3.x = fmaf(w7, v7.x, a3.x); a3.y = fmaf(w7, v7.y, a3.y);
        a3.z = fmaf(w7, v7.z, a3.z); a3.w = fmaf(w7, v7.w, a3.w);
    }
    for (; e < end; e++) {
        int   s = __ldg(&src[e]);
        float w = __ldg(&wgt[e]);
        float4 v = *reinterpret_cast<const float4*>(&xl[(size_t)s * FT]);
        a0.x = fmaf(w, v.x, a0.x); a0.y = fmaf(w, v.y, a0.y);
        a0.z = fmaf(w, v.z, a0.z); a0.w = fmaf(w, v.w, a0.w);
    }

    float4 s;
    s.x = (a0.x + a1.x) + (a2.x + a3.x);
    s.y = (a0.y + a1.y) + (a2.y + a3.y);
    s.z = (a0.z + a1.z) + (a2.z + a3.z);
    s.w = (a0.w + a1.w) + (a2.w + a3.w);
    *reinterpret_cast<float4*>(&emb[(size_t)gw * FT + lid * 4]) = s;
}

// ---------------------------------------------------------------------------
// Shared GEMM core (R11 structure): BM=128, BN=128, BK=16, 256 threads,
// 8x8 per-thread tile on packed fp32x2. A from `Asrc` rows, K=128.
// EPILOGUE selects: store raw (gemmX) or acc+bias+relu (gemmE).
// ---------------------------------------------------------------------------
#define BM 128
#define BN 128
#define BK 16

template <bool FINAL>
__device__ __forceinline__
void gemm_body(const float* __restrict__ Asrc,   // [M,128] row-major
               const float* __restrict__ W,      // [128,128] slice, row-major
               const float* __restrict__ accin,  // FINAL: partial products
               const float* __restrict__ bias,
               float* __restrict__ outp, int M) {
    __shared__ __align__(16) float As[BK][BM];   // 8 KB (k-major)
    __shared__ __align__(16) float Bs[BK][BN];   // 8 KB

    const int tid = threadIdx.x;
    const int tx = tid & 15;        // col groups: tx*4 and tx*4+64
    const int ty = tid >> 4;        // row groups of 8
    const int block_row = blockIdx.x * BM;

    unsigned long long acc[8][4];
    #pragma unroll
    for (int r = 0; r < 8; r++)
        #pragma unroll
        for (int j = 0; j < 4; j++) acc[r][j] = 0ull;

    for (int k0 = 0; k0 < FT; k0 += BK) {
        #pragma unroll
        for (int j = 0; j < 2; j++) {
            int idx  = tid + j * 256;
            int a_r  = idx >> 2;            // [0,128)
            int a_kq = (idx & 3) * 4;       // [0,16) step 4
            int grow = block_row + a_r;
            float4 v = make_float4(0.f, 0.f, 0.f, 0.f);
            if (grow < M)
                v = *reinterpret_cast<const float4*>(
                        &Asrc[(size_t)grow * FT + k0 + a_kq]);
            As[a_kq + 0][a_r] = v.x;
            As[a_kq + 1][a_r] = v.y;
            As[a_kq + 2][a_r] = v.z;
            As[a_kq + 3][a_r] = v.w;
        }
        #pragma unroll
        for (int j = 0; j < 2; j++) {
            int idx = tid + j * 256;
            int k   = idx >> 5;             // [0,16)
            int c4  = (idx & 31) * 4;       // [0,128) step 4
            float4 v = *reinterpret_cast<const float4*>(&W[(size_t)(k0 + k) * BN + c4]);
            *reinterpret_cast<float4*>(&Bs[k][c4]) = v;
        }
        __syncthreads();

        #pragma unroll
        for (int kk = 0; kk < BK; kk++) {
            float4 av0 = *reinterpret_cast<const float4*>(&As[kk][ty * 8]);
            float4 av1 = *reinterpret_cast<const float4*>(&As[kk][ty * 8 + 4]);
            ulonglong2 bp0 = *reinterpret_cast<const ulonglong2*>(&Bs[kk][tx * 4]);
            ulonglong2 bp1 = *reinterpret_cast<const ulonglong2*>(&Bs[kk][tx * 4 + 64]);
            unsigned long long b[4] = {bp0.x, bp0.y, bp1.x, bp1.y};
            unsigned long long pa[8];
            pa[0] = pack2(av0.x, av0.x);
            pa[1] = pack2(av0.y, av0.y);
            pa[2] = pack2(av0.z, av0.z);
            pa[3] = pack2(av0.w, av0.w);
            pa[4] = pack2(av1.x, av1.x);
            pa[5] = pack2(av1.y, av1.y);
            pa[6] = pack2(av1.z, av1.z);
            pa[7] = pack2(av1.w, av1.w);
            #pragma unroll
            for (int r = 0; r < 8; r++)
                #pragma unroll
                for (int j = 0; j < 4; j++)
                    acc[r][j] = fma2(pa[r], b[j], acc[r][j]);
        }
        __syncthreads();
    }

    float4 bb0, bb1;
    if (FINAL) {
        bb0 = *reinterpret_cast<const float4*>(&bias[tx * 4]);
        bb1 = *reinterpret_cast<const float4*>(&bias[tx * 4 + 64]);
    }

    #pragma unroll
    for (int r = 0; r < 8; r++) {
        int grow = block_row + ty * 8 + r;
        if (grow >= M) continue;
        float c0, c1, c2, c3, c4, c5, c6, c7;
        unpack2(acc[r][0], c0, c1);
        unpack2(acc[r][1], c2, c3);
        unpack2(acc[r][2], c4, c5);
        unpack2(acc[r][3], c6, c7);
        float4 o0, o1;
        if (FINAL) {
            float4 p0 = *reinterpret_cast<const float4*>(
                            &accin[(size_t)grow * BN + tx * 4]);
            float4 p1 = *reinterpret_cast<const float4*>(
                            &accin[(size_t)grow * BN + tx * 4 + 64]);
            o0.x = fmaxf(c0 + p0.x + bb0.x, 0.f);
            o0.y = fmaxf(c1 + p0.y + bb0.y, 0.f);
            o0.z = fmaxf(c2 + p0.z + bb0.z, 0.f);
            o0.w = fmaxf(c3 + p0.w + bb0.w, 0.f);
            o1.x = fmaxf(c4 + p1.x + bb1.x, 0.f);
            o1.y = fmaxf(c5 + p1.y + bb1.y, 0.f);
            o1.z = fmaxf(c6 + p1.z + bb1.z, 0.f);
            o1.w = fmaxf(c7 + p1.w + bb1.w, 0.f);
        } else {
            o0 = make_float4(c0, c1, c2, c3);
            o1 = make_float4(c4, c5, c6, c7);
        }
        *reinterpret_cast<float4*>(&outp[(size_t)grow * BN + tx * 4])      = o0;
        *reinterpret_cast<float4*>(&outp[(size_t)grow * BN + tx * 4 + 64]) = o1;
    }
}

// Kernel B (overlaps agg): acc = x @ W[0:128,:]
__global__ __launch_bounds__(256, 2)
void gemmX_kernel(const float* __restrict__ x, const float* __restrict__ W,
                  float* __restrict__ accout, int M) {
    gemm_body<false>(x, W, nullptr, nullptr, accout, M);
}

// Kernel C (after join): out = relu(acc + emb @ W[128:256,:] + bias)
__global__ __launch_bounds__(256, 2)
void gemmE_kernel(const float* __restrict__ emb, const float* __restrict__ W2,
                  const float* __restrict__ accin, const float* __restrict__ bias,
                  float* __restrict__ out, int M) {
    gemm_body<true>(emb, W2, accin, bias, out, M);
}

// ---------------------------------------------------------------------------
// Launch with fork-join stream overlap (graph-capturable pattern):
//   default stream: gemmX  ||  side stream: agg   -> join -> gemmE
// Inputs (metadata order): 0:x f32, 1:edge_src i32, 2:edge_dst i32 (sorted),
//   3:edge_weight f32, 4:weight [256*128] f32, 5:bias [128] f32
// ---------------------------------------------------------------------------
extern "C" void kernel_launch(void* const* d_in, const int* in_sizes, int n_in,
                              void* d_out, int out_size) {
    const float* x    = (const float*)d_in[0];
    const int*   esrc = (const int*)d_in[1];
    const int*   edst = (const int*)d_in[2];
    const float* ewgt = (const float*)d_in[3];
    const float* W    = (const float*)d_in[4];
    const float* bias = (const float*)d_in[5];
    float* out = (float*)d_out;

    int Nn = in_sizes[0] / FT;
    int E  = in_sizes[1];

    float *emb, *acc;
    cudaGetSymbolAddress((void**)&emb, g_emb);
    cudaGetSymbolAddress((void**)&acc, g_acc);

    static cudaStream_t s_side = nullptr;
    static cudaEvent_t  ev_fork = nullptr, ev_join = nullptr;
    if (s_side == nullptr) {
        cudaStreamCreateWithFlags(&s_side, cudaStreamNonBlocking);
        cudaEventCreateWithFlags(&ev_fork, cudaEventDisableTiming);
        cudaEventCreateWithFlags(&ev_join, cudaEventDisableTiming);
    }

    // fork: side stream inherits current default-stream state
    cudaEventRecord(ev_fork, 0);
    cudaStreamWaitEvent(s_side, ev_fork, 0);

    // side stream: L2-gather-bound aggregation
    agg_kernel<<<(Nn * 32 + 255) / 256, 256, 0, s_side>>>(
        x, esrc, edst, ewgt, emb, Nn, E);

    // default stream (concurrent): FMA-bound x @ W1
    gemmX_kernel<<<(Nn + BM - 1) / BM, 256>>>(x, W, acc, Nn);

    // join
    cudaEventRecord(ev_join, s_side);
    cudaStreamWaitEvent(0, ev_join, 0);

    // final: out = relu(acc + emb @ W2 + bias)
    gemmE_kernel<<<(Nn + BM - 1) / BM, 256>>>(emb, W + (size_t)FT * FT,
                                              acc, bias, out, Nn);
}

// round 17
// speedup vs baseline: 1.1605x; 1.1605x over previous
#include <cuda_runtime.h>
#include <cuda_bf16.h>
#include <cstdint>

// Problem constants (fixed by dataset): N=50000, E=800000, IN=OUT=128, fp32.
#define FT        128
#define BM        128
#define BN        128
#define BK        16
#define EMB_PITCH 132   // 128 + 4 pad: bank-skewed 528B row pitch, 16B aligned

// smem layout (floats): emb_s[128*132] | As[16*128] | Bs[16*128] | rp[129]
#define SM_EMB   0
#define SM_AS    (BM * EMB_PITCH)
#define SM_BS    (SM_AS + BK * BM)
#define SM_RP    (SM_BS + BK * BN)
#define SMEM_FLOATS (SM_RP + 132)
#define SMEM_BYTES  (SMEM_FLOATS * 4)

// ---------------------------------------------------------------------------
// Packed fp32x2 helpers (FFMA2 in SASS — 2x fp32 FMA throughput, bit-exact)
// ---------------------------------------------------------------------------
__device__ __forceinline__ unsigned long long fma2(unsigned long long a,
                                                   unsigned long long b,
                                                   unsigned long long c) {
    unsigned long long d;
    asm("fma.rn.f32x2 %0, %1, %2, %3;" : "=l"(d) : "l"(a), "l"(b), "l"(c));
    return d;
}
__device__ __forceinline__ unsigned long long pack2(float lo, float hi) {
    unsigned long long d;
    asm("mov.b64 %0, {%1, %2};" : "=l"(d) : "f"(lo), "f"(hi));
    return d;
}
__device__ __forceinline__ void unpack2(unsigned long long v, float& lo, float& hi) {
    asm("mov.b64 {%0, %1}, %2;" : "=f"(lo), "=f"(hi) : "l"(v));
}

// ---------------------------------------------------------------------------
// Aggregation phase (block-local): warp per node, 16 nodes per warp,
// 4-way edge unroll (register-budget-friendly: acc tile may be live).
// ---------------------------------------------------------------------------
__device__ __forceinline__ void agg_phase(const float* __restrict__ x,
                                          const int* __restrict__ src,
                                          const float* __restrict__ wgt,
                                          const int* rp, float* emb_s, int tid) {
    const int wid = tid >> 5;
    const int lid = tid & 31;
    const float* xl = x + lid * 4;
    #pragma unroll 1
    for (int t = 0; t < 16; t++) {
        int ln = wid * 16 + t;
        int start = rp[ln];
        int end   = rp[ln + 1];
        float4 a0 = make_float4(0.f, 0.f, 0.f, 0.f);
        float4 a1 = a0, a2 = a0, a3 = a0;
        int e = start;
        int e4 = start + ((end - start) & ~3);
        for (; e < e4; e += 4) {
            int   s0 = __ldg(&src[e + 0]), s1 = __ldg(&src[e + 1]);
            int   s2 = __ldg(&src[e + 2]), s3 = __ldg(&src[e + 3]);
            float w0 = __ldg(&wgt[e + 0]), w1 = __ldg(&wgt[e + 1]);
            float w2 = __ldg(&wgt[e + 2]), w3 = __ldg(&wgt[e + 3]);
            float4 v0 = *reinterpret_cast<const float4*>(&xl[(size_t)s0 * FT]);
            float4 v1 = *reinterpret_cast<const float4*>(&xl[(size_t)s1 * FT]);
            float4 v2 = *reinterpret_cast<const float4*>(&xl[(size_t)s2 * FT]);
            float4 v3 = *reinterpret_cast<const float4*>(&xl[(size_t)s3 * FT]);
            a0.x = fmaf(w0, v0.x, a0.x); a0.y = fmaf(w0, v0.y, a0.y);
            a0.z = fmaf(w0, v0.z, a0.z); a0.w = fmaf(w0, v0.w, a0.w);
            a1.x = fmaf(w1, v1.x, a1.x); a1.y = fmaf(w1, v1.y, a1.y);
            a1.z = fmaf(w1, v1.z, a1.z); a1.w = fmaf(w1, v1.w, a1.w);
            a2.x = fmaf(w2, v2.x, a2.x); a2.y = fmaf(w2, v2.y, a2.y);
            a2.z = fmaf(w2, v2.z, a2.z); a2.w = fmaf(w2, v2.w, a2.w);
            a3.x = fmaf(w3, v3.x, a3.x); a3.y = fmaf(w3, v3.y, a3.y);
            a3.z = fmaf(w3, v3.z, a3.z); a3.w = fmaf(w3, v3.w, a3.w);
        }
        for (; e < end; e++) {
            int   s = __ldg(&src[e]);
            float w = __ldg(&wgt[e]);
            float4 v = *reinterpret_cast<const float4*>(&xl[(size_t)s * FT]);
            a0.x = fmaf(w, v.x, a0.x); a0.y = fmaf(w, v.y, a0.y);
            a0.z = fmaf(w, v.z, a0.z); a0.w = fmaf(w, v.w, a0.w);
        }
        float4 r;
        r.x = (a0.x + a1.x) + (a2.x + a3.x);
        r.y = (a0.y + a1.y) + (a2.y + a3.y);
        r.z = (a0.z + a1.z) + (a2.z + a3.z);
        r.w = (a0.w + a1.w) + (a2.w + a3.w);
        *reinterpret_cast<float4*>(&emb_s[ln * EMB_PITCH + lid * 4]) = r;
    }
}

// ---------------------------------------------------------------------------
// GEMM k-range [KBEG, KEND): R12 structure (8x8 FFMA2, 1.0 LDS-B/FMA,
// conflict-free B reads). KBEG==0 zeroes the accumulators.
// k < 128 -> A from global x; k >= 128 -> A from smem emb_s.
// ---------------------------------------------------------------------------
template <int KBEG, int KEND>
__device__ __forceinline__ void gemm_part(const float* __restrict__ x,
                                          const float* emb_s,
                                          float* As, float* Bs,
                                          const float* __restrict__ W,
                                          int block_row, int M, int tid,
                                          unsigned long long acc[8][4]) {
    const int tx = tid & 15;
    const int ty = tid >> 4;

    if (KBEG == 0) {
        #pragma unroll
        for (int r = 0; r < 8; r++)
            #pragma unroll
            for (int j = 0; j < 4; j++) acc[r][j] = 0ull;
    }

    for (int k0 = KBEG; k0 < KEND; k0 += BK) {
        const bool from_x = (k0 < FT);
        #pragma unroll
        for (int j = 0; j < 2; j++) {
            int idx  = tid + j * 256;
            int a_r  = idx >> 2;            // [0,128)
            int a_kq = (idx & 3) * 4;       // [0,16) step 4
            float4 v;
            if (from_x) {
                int grow = block_row + a_r;
                v = make_float4(0.f, 0.f, 0.f, 0.f);
                if (grow < M)
                    v = *reinterpret_cast<const float4*>(
                            &x[(size_t)grow * FT + k0 + a_kq]);
            } else {
                v = *reinterpret_cast<const float4*>(
                        &emb_s[a_r * EMB_PITCH + (k0 - FT) + a_kq]);
            }
            As[(a_kq + 0) * BM + a_r] = v.x;
            As[(a_kq + 1) * BM + a_r] = v.y;
            As[(a_kq + 2) * BM + a_r] = v.z;
            As[(a_kq + 3) * BM + a_r] = v.w;
        }
        #pragma unroll
        for (int j = 0; j < 2; j++) {
            int idx = tid + j * 256;
            int k   = idx >> 5;             // [0,16)
            int c4  = (idx & 31) * 4;       // [0,128) step 4
            float4 v = *reinterpret_cast<const float4*>(&W[(size_t)(k0 + k) * BN + c4]);
            *reinterpret_cast<float4*>(&Bs[k * BN + c4]) = v;
        }
        __syncthreads();

        #pragma unroll
        for (int kk = 0; kk < BK; kk++) {
            float4 av0 = *reinterpret_cast<const float4*>(&As[kk * BM + ty * 8]);
            float4 av1 = *reinterpret_cast<const float4*>(&As[kk * BM + ty * 8 + 4]);
            ulonglong2 bp0 = *reinterpret_cast<const ulonglong2*>(&Bs[kk * BN + tx * 4]);
            ulonglong2 bp1 = *reinterpret_cast<const ulonglong2*>(&Bs[kk * BN + tx * 4 + 64]);
            unsigned long long b[4] = {bp0.x, bp0.y, bp1.x, bp1.y};
            unsigned long long pa[8];
            pa[0] = pack2(av0.x, av0.x);
            pa[1] = pack2(av0.y, av0.y);
            pa[2] = pack2(av0.z, av0.z);
            pa[3] = pack2(av0.w, av0.w);
            pa[4] = pack2(av1.x, av1.x);
            pa[5] = pack2(av1.y, av1.y);
            pa[6] = pack2(av1.z, av1.z);
            pa[7] = pack2(av1.w, av1.w);
            #pragma unroll
            for (int r = 0; r < 8; r++)
                #pragma unroll
                for (int j = 0; j < 4; j++)
                    acc[r][j] = fma2(pa[r], b[j], acc[r][j]);
        }
        __syncthreads();
    }
}

// ---------------------------------------------------------------------------
// FUSED kernel with PARITY-STAGGERED phases:
//   even blocks: agg -> x-GEMM -> emb-GEMM
//   odd  blocks: x-GEMM -> agg -> emb-GEMM
// Adjacent bids land on the same SM (2 blocks/SM, contiguous placement), so
// each SM statically runs one L2-gather phase against one FMA phase.
// ---------------------------------------------------------------------------
__global__ __launch_bounds__(256, 2)
void fused_kernel(const float* __restrict__ x,
                  const int* __restrict__ src,
                  const int* __restrict__ dst,
                  const float* __restrict__ wgt,
                  const float* __restrict__ W,     // [256,128] row-major
                  const float* __restrict__ bias,  // [128]
                  float* __restrict__ out,
                  int M, int E) {
    extern __shared__ float sm[];
    float* emb_s = sm + SM_EMB;
    float* As    = sm + SM_AS;
    float* Bs    = sm + SM_BS;
    int*   rp    = (int*)(sm + SM_RP);

    const int tid = threadIdx.x;
    const int block_row = blockIdx.x * BM;

    // phase 0: block-local CSR row pointers (129 boundaries)
    if (tid <= BM) {
        int target = block_row + tid;
        int lo = 0, hi = E;
        while (lo < hi) {
            int mid = (lo + hi) >> 1;
            if (__ldg(&dst[mid]) < target) lo = mid + 1; else hi = mid;
        }
        rp[tid] = lo;
    }
    __syncthreads();

    unsigned long long acc[8][4];

    if ((blockIdx.x & 1) == 0) {
        // even: gather first, compute second
        agg_phase(x, src, wgt, rp, emb_s, tid);
        __syncthreads();
        gemm_part<0, 128>(x, emb_s, As, Bs, W, block_row, M, tid, acc);
        gemm_part<128, 256>(x, emb_s, As, Bs, W, block_row, M, tid, acc);
    } else {
        // odd: x-half GEMM first (no agg dependency), gather second
        gemm_part<0, 128>(x, emb_s, As, Bs, W, block_row, M, tid, acc);
        agg_phase(x, src, wgt, rp, emb_s, tid);
        __syncthreads();
        gemm_part<128, 256>(x, emb_s, As, Bs, W, block_row, M, tid, acc);
    }

    // epilogue: + bias, relu, two float4 stores per row
    const int tx = tid & 15;
    const int ty = tid >> 4;
    float4 bb0 = *reinterpret_cast<const float4*>(&bias[tx * 4]);
    float4 bb1 = *reinterpret_cast<const float4*>(&bias[tx * 4 + 64]);

    #pragma unroll
    for (int r = 0; r < 8; r++) {
        int grow = block_row + ty * 8 + r;
        if (grow >= M) continue;
        float c0, c1, c2, c3, c4, c5, c6, c7;
        unpack2(acc[r][0], c0, c1);
        unpack2(acc[r][1], c2, c3);
        unpack2(acc[r][2], c4, c5);
        unpack2(acc[r][3], c6, c7);
        float4 o0, o1;
        o0.x = fmaxf(c0 + bb0.x, 0.f);
        o0.y = fmaxf(c1 + bb0.y, 0.f);
        o0.z = fmaxf(c2 + bb0.z, 0.f);
        o0.w = fmaxf(c3 + bb0.w, 0.f);
        o1.x = fmaxf(c4 + bb1.x, 0.f);
        o1.y = fmaxf(c5 + bb1.y, 0.f);
        o1.z = fmaxf(c6 + bb1.z, 0.f);
        o1.w = fmaxf(c7 + bb1.w, 0.f);
        *reinterpret_cast<float4*>(&out[(size_t)grow * BN + tx * 4])      = o0;
        *reinterpret_cast<float4*>(&out[(size_t)grow * BN + tx * 4 + 64]) = o1;
    }
}

// ---------------------------------------------------------------------------
// Launch. Inputs (metadata order):
//   0: x [N*128] f32, 1: edge_src [E] i32, 2: edge_dst [E] i32 (sorted),
//   3: edge_weight [E] f32, 4: weight [256*128] f32, 5: bias [128] f32
// ---------------------------------------------------------------------------
extern "C" void kernel_launch(void* const* d_in, const int* in_sizes, int n_in,
                              void* d_out, int out_size) {
    const float* x    = (const float*)d_in[0];
    const int*   esrc = (const int*)d_in[1];
    const int*   edst = (const int*)d_in[2];
    const float* ewgt = (const float*)d_in[3];
    const float* W    = (const float*)d_in[4];
    const float* bias = (const float*)d_in[5];
    float* out = (float*)d_out;

    int Nn = in_sizes[0] / FT;
    int E  = in_sizes[1];

    static bool attr_set = false;
    if (!attr_set) {
        cudaFuncSetAttribute(fused_kernel,
                             cudaFuncAttributeMaxDynamicSharedMemorySize,
                             SMEM_BYTES);
        attr_set = true;
    }

    int grid = (Nn + BM - 1) / BM;
    fused_kernel<<<grid, 256, SMEM_BYTES>>>(x, esrc, edst, ewgt, W, bias,
                                            out, Nn, E);
}